// round 10
// baseline (speedup 1.0000x reference)
#include <cuda_runtime.h>
#include <cuda_fp16.h>
#include <cstdint>

#define Nn 4096
#define DI 512
#define DO 128
#define NH 4
#define BM 128
#define BK 64            // fused stage width (was 32): half the barriers
#define BSTR 36          // hgemm pair-permuted tile stride (floats)
#define WSTR 132         // hgemm W tile stride
#define HSTR 80          // fused tile row stride in halfs (160 B, conflict-free)
#define TILEH (BM * HSTR)  // 10240 halfs = 20 KB per tile

// ---------------- device scratch ----------------
__device__ __half g_hT[DO * Nn];   // h fp16, transposed [d][node] (B operand)
__device__ float g_p[NH * Nn], g_p2[NH * Nn];   // exp(el), exp(0.2 el)
__device__ float g_q[NH * Nn], g_q2[NH * Nn];   // exp(er), exp(0.2 er)

// ---------------- helpers ----------------
__device__ __forceinline__ uint32_t cvt_tf32(float x) {
    uint32_t r;
    asm("cvt.rna.tf32.f32 %0, %1;" : "=r"(r) : "f"(x));
    return r;
}
__device__ __forceinline__ void mma_tf32(float& c0, float& c1, float& c2, float& c3,
                                         uint32_t a0, uint32_t a1, uint32_t a2, uint32_t a3,
                                         uint32_t b0, uint32_t b1) {
    asm volatile("mma.sync.aligned.m16n8k8.row.col.f32.tf32.tf32.f32 "
                 "{%0,%1,%2,%3}, {%4,%5,%6,%7}, {%8,%9}, {%0,%1,%2,%3};"
                 : "+f"(c0), "+f"(c1), "+f"(c2), "+f"(c3)
                 : "r"(a0), "r"(a1), "r"(a2), "r"(a3), "r"(b0), "r"(b1));
}
__device__ __forceinline__ void mma_f16(float& c0, float& c1, float& c2, float& c3,
                                        uint32_t a0, uint32_t a1, uint32_t a2, uint32_t a3,
                                        uint32_t b0, uint32_t b1) {
    asm volatile("mma.sync.aligned.m16n8k16.row.col.f32.f16.f16.f32 "
                 "{%0,%1,%2,%3}, {%4,%5,%6,%7}, {%8,%9}, {%0,%1,%2,%3};"
                 : "+f"(c0), "+f"(c1), "+f"(c2), "+f"(c3)
                 : "r"(a0), "r"(a1), "r"(a2), "r"(a3), "r"(b0), "r"(b1));
}
__device__ __forceinline__ void lds64(uint32_t& x, uint32_t& y, const void* p) {
    asm volatile("ld.shared.v2.b32 {%0,%1}, [%2];" : "=r"(x), "=r"(y) : "l"(__cvta_generic_to_shared(p)));
}
__device__ __forceinline__ void sts32(void* p, uint32_t v) {
    asm volatile("st.shared.b32 [%0], %1;" :: "l"(__cvta_generic_to_shared(p)), "r"(v));
}
// pair-permutation for fp32 tiles (hgemm): (j, j+4) adjacent
__device__ __forceinline__ int posk(int j) {
    return (j & 24) + ((j & 3) << 1) + ((j >> 2) & 1);
}
// half-tile word permutation (per 16-col chunk): word = chunk*8 + ((p&3)<<1|(p>>2))
__device__ __forceinline__ int halfword(int c) {
    int chunk = c >> 4, p = (c & 15) >> 1;
    return chunk * 8 + ((p & 3) << 1) + (p >> 2);
}

// ======================================================================
// Kernel 1: h = x @ W via mma.sync tf32, software-pipelined (round-8 WIN),
// with k_node FUSED into the epilogue: h rows staged to smem, attention
// projections + factorized exps computed in-CTA. No g_h global array.
// ======================================================================
__global__ __launch_bounds__(256) void k_hgemm(const float* __restrict__ x,
                                               const float* __restrict__ W,
                                               const float* __restrict__ al,
                                               const float* __restrict__ ar) {
    __shared__ float xs[2][32 * BSTR];
    __shared__ float Ws[2][32 * WSTR];

    int t = threadIdx.x, lane = t & 31, warp = t >> 5;
    int g = lane >> 2, ctg = lane & 3;
    int i0 = blockIdx.x * 32;
    int wm = warp >> 2, wn = warp & 3;
    int rmA = wm * 16 + g;
    int n0 = wn * 32;

    float acc[4][4];
#pragma unroll
    for (int nt = 0; nt < 4; nt++)
#pragma unroll
        for (int c = 0; c < 4; c++) acc[nt][c] = 0.0f;

    int xrow = t >> 3, xkq = (t & 7) * 4;
    const float* xp = &x[(size_t)(i0 + xrow) * DI + xkq];

    float4 xv;
    float4 wv[4];

#define HG_LDG(K0)                                                              \
    do {                                                                        \
        xv = *reinterpret_cast<const float4*>(xp + (K0));                       \
        _Pragma("unroll")                                                       \
        for (int r = 0; r < 4; r++) {                                           \
            int f = t + 256 * r;                                                \
            int kr = f >> 5, nc = (f & 31) * 4;                                 \
            wv[r] = *reinterpret_cast<const float4*>(&W[(size_t)((K0) + kr) * DO + nc]); \
        }                                                                       \
    } while (0)

#define HG_STS(S)                                                               \
    do {                                                                        \
        float* dst = &xs[S][xrow * BSTR];                                       \
        dst[posk(xkq + 0)] = __uint_as_float(cvt_tf32(xv.x));                   \
        dst[posk(xkq + 1)] = __uint_as_float(cvt_tf32(xv.y));                   \
        dst[posk(xkq + 2)] = __uint_as_float(cvt_tf32(xv.z));                   \
        dst[posk(xkq + 3)] = __uint_as_float(cvt_tf32(xv.w));                   \
        _Pragma("unroll")                                                       \
        for (int r = 0; r < 4; r++) {                                           \
            int f = t + 256 * r;                                                \
            int kr = f >> 5, nc = (f & 31) * 4;                                 \
            float* wd = &Ws[S][kr * WSTR + nc];                                 \
            wd[0] = __uint_as_float(cvt_tf32(wv[r].x));                         \
            wd[1] = __uint_as_float(cvt_tf32(wv[r].y));                         \
            wd[2] = __uint_as_float(cvt_tf32(wv[r].z));                         \
            wd[3] = __uint_as_float(cvt_tf32(wv[r].w));                         \
        }                                                                       \
    } while (0)

    HG_LDG(0);
    HG_STS(0);
    HG_LDG(32);

    const int NST = DI / 32;   // 16
    for (int it = 0; it < NST; ++it) {
        __syncthreads();
        if (it + 1 < NST) {
            HG_STS((it + 1) & 1);
            int nk = (it + 2 < NST) ? (it + 2) * 32 : 0;
            HG_LDG(nk);
        }
        const float* xsb = xs[it & 1];
        const float* Wsb = Ws[it & 1];
#pragma unroll
        for (int kk = 0; kk < 4; kk++) {
            uint32_t a0, a2, a1, a3;
            lds64(a0, a2, &xsb[rmA * BSTR + kk * 8 + ctg * 2]);
            lds64(a1, a3, &xsb[(rmA + 8) * BSTR + kk * 8 + ctg * 2]);
#pragma unroll
            for (int nt = 0; nt < 4; nt++) {
                int n = n0 + nt * 8 + g;
                uint32_t b0 = __float_as_uint(Wsb[(kk * 8 + ctg) * WSTR + n]);
                uint32_t b1 = __float_as_uint(Wsb[(kk * 8 + ctg + 4) * WSTR + n]);
                mma_tf32(acc[nt][0], acc[nt][1], acc[nt][2], acc[nt][3],
                         a0, a1, a2, a3, b0, b1);
            }
        }
    }
#undef HG_LDG
#undef HG_STS

    // ---- epilogue A: write g_hT (fp16) + stage h rows into smem ----
    // Reuse Ws[0] area (4224 floats = 32 rows x stride 132) for h rows.
    // Safe: buffer 0 last touched at stage 14; all warps passed sync(it=15).
    float* hrow_s = &Ws[0][0];
    int lrA = rmA, lrB = rmA + 8;
    int rA = i0 + lrA, rB = i0 + lrB;
#pragma unroll
    for (int nt = 0; nt < 4; nt++) {
        int col = n0 + nt * 8 + ctg * 2;
        hrow_s[lrA * 132 + col]     = acc[nt][0];
        hrow_s[lrA * 132 + col + 1] = acc[nt][1];
        hrow_s[lrB * 132 + col]     = acc[nt][2];
        hrow_s[lrB * 132 + col + 1] = acc[nt][3];
        g_hT[(size_t)col * Nn + rA]       = __float2half_rn(acc[nt][0]);
        g_hT[(size_t)(col + 1) * Nn + rA] = __float2half_rn(acc[nt][1]);
        g_hT[(size_t)col * Nn + rB]       = __float2half_rn(acc[nt][2]);
        g_hT[(size_t)(col + 1) * Nn + rB] = __float2half_rn(acc[nt][3]);
    }
    __syncthreads();

    // ---- epilogue B: per-node projections + exps (was k_node) ----
    // warp w handles rows 4w..4w+3
    float alv[NH][4], arv[NH][4];
#pragma unroll
    for (int hd = 0; hd < NH; hd++)
#pragma unroll
        for (int k = 0; k < 4; k++) {
            alv[hd][k] = al[hd * DO + lane + 32 * k];
            arv[hd][k] = ar[hd * DO + lane + 32 * k];
        }
#pragma unroll
    for (int r = 0; r < 4; r++) {
        int row = warp * 4 + r;
        int node = i0 + row;
        float h0 = hrow_s[row * 132 + lane];
        float h1 = hrow_s[row * 132 + lane + 32];
        float h2 = hrow_s[row * 132 + lane + 64];
        float h3 = hrow_s[row * 132 + lane + 96];
#pragma unroll
        for (int hd = 0; hd < NH; hd++) {
            float sl = h0 * alv[hd][0] + h1 * alv[hd][1] + h2 * alv[hd][2] + h3 * alv[hd][3];
            float sr = h0 * arv[hd][0] + h1 * arv[hd][1] + h2 * arv[hd][2] + h3 * arv[hd][3];
#pragma unroll
            for (int off = 16; off; off >>= 1) {
                sl += __shfl_xor_sync(0xffffffffu, sl, off);
                sr += __shfl_xor_sync(0xffffffffu, sr, off);
            }
            if (lane == 0) {
                int idx = hd * Nn + node;
                g_p[idx]  = expf(sl);
                g_p2[idx] = expf(0.2f * sl);
                g_q[idx]  = expf(sr);
                g_q2[idx] = expf(0.2f * sr);
            }
        }
    }
}

// ======================================================================
// Kernel 2: fused masked-attention GEMM, fp16 m16n8k16, BK=64 stages,
// single-barrier software pipeline (round-7 structure), HSTR=80 tiles.
// Branch select via (p_i*q_j >= 1) <=> (el+er >= 0)  [validated round 8].
// ======================================================================
__global__ __launch_bounds__(512, 1) void k_fused(const float* __restrict__ adj,
                                                  const float* __restrict__ bias,
                                                  float* __restrict__ out) {
    extern __shared__ __half dsm[];    // [w0][w1][h0][h1], each TILEH halfs
    __shared__ float rowsum_s[BM];

    int t = threadIdx.x, lane = t & 31, warp = t >> 5;
    int g = lane >> 2, ctg = lane & 3;
    int head = blockIdx.x;
    int i0   = blockIdx.y * BM;
    int rm   = (warp >> 2) * 32;
    int n0   = (warp & 3) * 32;

    // i-side per-row factors (rows warp + 16*i)
    float pi[8], p2i[8], rsum[8];
#pragma unroll
    for (int i = 0; i < 8; i++) {
        int idx = head * Nn + i0 + warp + 16 * i;
        pi[i] = g_p[idx]; p2i[i] = g_p2[idx];
        rsum[i] = 0.0f;
    }
    const float* adj_base = adj + (size_t)(i0 + warp) * Nn + lane;
    const float* q_base   = g_q  + head * Nn + lane;
    const float* q2_base  = g_q2 + head * Nn + lane;
    int whalf0 = halfword(lane) * 2 + (lane & 1);   // j = lane
    // j = lane+32 lives 16 words further:  whalf1 = whalf0 + 32
    int hn = t >> 2, hc = t & 3;                    // h staging: row, 16-col chunk
    const __half* hT_base = g_hT + (size_t)hn * Nn + hc * 16;

    float acc[2][4][4];
#pragma unroll
    for (int mt = 0; mt < 2; mt++)
#pragma unroll
        for (int nt = 0; nt < 4; nt++)
#pragma unroll
            for (int c = 0; c < 4; c++) acc[mt][nt][c] = 0.0f;

    float areg0[8], areg1[8];
    uint4 hu0, hu1;
    float qj0, q2j0, qj1, q2j1;

#define FU_LDG(K0)                                                            \
    do {                                                                      \
        _Pragma("unroll")                                                     \
        for (int i = 0; i < 8; i++) {                                         \
            areg0[i] = adj_base[(size_t)(16 * i) * Nn + (K0)];                \
            areg1[i] = adj_base[(size_t)(16 * i) * Nn + (K0) + 32];           \
        }                                                                     \
        hu0 = *reinterpret_cast<const uint4*>(hT_base + (K0));                \
        hu1 = *reinterpret_cast<const uint4*>(hT_base + (K0) + 8);            \
        qj0 = q_base[K0];  q2j0 = q2_base[K0];                                \
        qj1 = q_base[(K0) + 32];  q2j1 = q2_base[(K0) + 32];                  \
    } while (0)

#define FU_PROD(S)                                                            \
    do {                                                                      \
        __half* ws = dsm + (S) * TILEH;                                       \
        __half* hs = dsm + 2 * TILEH + (S) * TILEH;                           \
        _Pragma("unroll")                                                     \
        for (int i = 0; i < 8; i++) {                                         \
            float pqa  = pi[i] * qj0;                                         \
            float pqa2 = p2i[i] * q2j0;                                       \
            float wa = areg0[i] * ((pqa >= 1.0f) ? pqa : pqa2);               \
            __half wha = __float2half_rn(wa);                                 \
            rsum[i] += __half2float(wha);                                     \
            float pqb  = pi[i] * qj1;                                         \
            float pqb2 = p2i[i] * q2j1;                                       \
            float wb = areg1[i] * ((pqb >= 1.0f) ? pqb : pqb2);               \
            __half whb = __float2half_rn(wb);                                 \
            rsum[i] += __half2float(whb);                                     \
            __half* wr = &ws[(warp + 16 * i) * HSTR];                         \
            wr[whalf0]      = wha;                                            \
            wr[whalf0 + 32] = whb;                                            \
        }                                                                     \
        __half* hd = &hs[hn * HSTR];                                          \
        sts32(hd + (hc * 8 + 0) * 2, hu0.x);                                  \
        sts32(hd + (hc * 8 + 2) * 2, hu0.y);                                  \
        sts32(hd + (hc * 8 + 4) * 2, hu0.z);                                  \
        sts32(hd + (hc * 8 + 6) * 2, hu0.w);                                  \
        sts32(hd + (hc * 8 + 1) * 2, hu1.x);                                  \
        sts32(hd + (hc * 8 + 3) * 2, hu1.y);                                  \
        sts32(hd + (hc * 8 + 5) * 2, hu1.z);                                  \
        sts32(hd + (hc * 8 + 7) * 2, hu1.w);                                  \
    } while (0)

    // ---- prologue ----
    FU_LDG(0);
    FU_PROD(0);
    FU_LDG(BK);

    const int NIT = Nn / BK;   // 64
    for (int it = 0; it < NIT; ++it) {
        __syncthreads();   // produce(it) visible; mma(it-1) done everywhere

        if (it + 1 < NIT) {
            FU_PROD((it + 1) & 1);
            int nk0 = (it + 2 < NIT) ? (it + 2) * BK : 0;
            FU_LDG(nk0);
        }

        // ---- mma(it) on buffer it&1: 4 k16 chunks x 2 mt x 4 nt ----
        {
            const __half* ws = dsm + (it & 1) * TILEH;
            const __half* hs = dsm + 2 * TILEH + (it & 1) * TILEH;
#pragma unroll
            for (int kk = 0; kk < 4; kk++) {
                int koff = (kk * 8 + 2 * ctg) * 2;
                uint32_t b0[4], b1[4];
#pragma unroll
                for (int nt = 0; nt < 4; nt++)
                    lds64(b0[nt], b1[nt], &hs[(n0 + nt * 8 + g) * HSTR + koff]);
#pragma unroll
                for (int mt = 0; mt < 2; mt++) {
                    uint32_t a0, a2, a1, a3;
                    lds64(a0, a2, &ws[(rm + mt * 16 + g) * HSTR + koff]);
                    lds64(a1, a3, &ws[(rm + mt * 16 + 8 + g) * HSTR + koff]);
#pragma unroll
                    for (int nt = 0; nt < 4; nt++)
                        mma_f16(acc[mt][nt][0], acc[mt][nt][1], acc[mt][nt][2], acc[mt][nt][3],
                                a0, a1, a2, a3, b0[nt], b1[nt]);
                }
            }
        }
    }
#undef FU_LDG
#undef FU_PROD

    // ---- rowsum reduce across lanes ----
#pragma unroll
    for (int i = 0; i < 8; i++) {
        float v = rsum[i];
#pragma unroll
        for (int off = 16; off; off >>= 1) v += __shfl_xor_sync(0xffffffffu, v, off);
        if (lane == 0) rowsum_s[warp + 16 * i] = v;
    }
    __syncthreads();

    // ---- epilogue: normalize + bias + store ----
#pragma unroll
    for (int mt = 0; mt < 2; mt++) {
        int lrA = rm + mt * 16 + g;
        int lrB = lrA + 8;
        float invA = 1.0f / fmaxf(rowsum_s[lrA], 1e-12f);
        float invB = 1.0f / fmaxf(rowsum_s[lrB], 1e-12f);
#pragma unroll
        for (int nt = 0; nt < 4; nt++) {
            int bcol = n0 + nt * 8 + ctg * 2;
            float2 bv = *reinterpret_cast<const float2*>(&bias[bcol]);
            float* opA = out + (size_t)(i0 + lrA) * (NH * DO) + head * DO + bcol;
            float* opB = out + (size_t)(i0 + lrB) * (NH * DO) + head * DO + bcol;
            *reinterpret_cast<float2*>(opA) =
                make_float2(acc[mt][nt][0] * invA + bv.x, acc[mt][nt][1] * invA + bv.y);
            *reinterpret_cast<float2*>(opB) =
                make_float2(acc[mt][nt][2] * invB + bv.x, acc[mt][nt][3] * invB + bv.y);
        }
    }
}

// ======================================================================
extern "C" void kernel_launch(void* const* d_in, const int* in_sizes, int n_in,
                              void* d_out, int out_size) {
    const float* adj = (const float*)d_in[0];
    const float* x   = (const float*)d_in[1];
    const float* W   = (const float*)d_in[2];
    const float* al  = (const float*)d_in[3];
    const float* ar  = (const float*)d_in[4];
    const float* b   = (const float*)d_in[5];
    float* out = (float*)d_out;

    const int dyn = 4 * TILEH * sizeof(__half);   // 81920 B
    cudaFuncSetAttribute(k_fused, cudaFuncAttributeMaxDynamicSharedMemorySize, dyn);

    k_hgemm<<<Nn / 32, 256>>>(x, W, al, ar);
    k_fused<<<dim3(NH, Nn / BM), 512, dyn>>>(adj, b, out);
}

// round 11
// speedup vs baseline: 1.0561x; 1.0561x over previous
#include <cuda_runtime.h>
#include <cuda_fp16.h>
#include <cstdint>

#define Nn 4096
#define DI 512
#define DO 128
#define NH 4
#define BM 128
#define BK 32
#define BSTR 36          // hgemm pair-permuted tile stride (floats)
#define WSTR 132         // hgemm W tile stride
#define HSTR 48          // fused tile row stride in halfs (96 B)
#define TILEH (BM * HSTR)  // 6144 halfs = 12 KB per tile

// ---------------- device scratch ----------------
__device__ __half g_hT[DO * Nn];   // h fp16, transposed [d][node] (B operand)
__device__ float g_el[NH * Nn], g_p[NH * Nn], g_p2[NH * Nn];
__device__ float g_er[NH * Nn], g_q[NH * Nn], g_q2[NH * Nn];

// ---------------- helpers ----------------
__device__ __forceinline__ uint32_t cvt_tf32(float x) {
    uint32_t r;
    asm("cvt.rna.tf32.f32 %0, %1;" : "=r"(r) : "f"(x));
    return r;
}
__device__ __forceinline__ void mma_tf32(float& c0, float& c1, float& c2, float& c3,
                                         uint32_t a0, uint32_t a1, uint32_t a2, uint32_t a3,
                                         uint32_t b0, uint32_t b1) {
    asm volatile("mma.sync.aligned.m16n8k8.row.col.f32.tf32.tf32.f32 "
                 "{%0,%1,%2,%3}, {%4,%5,%6,%7}, {%8,%9}, {%0,%1,%2,%3};"
                 : "+f"(c0), "+f"(c1), "+f"(c2), "+f"(c3)
                 : "r"(a0), "r"(a1), "r"(a2), "r"(a3), "r"(b0), "r"(b1));
}
__device__ __forceinline__ void mma_f16(float& c0, float& c1, float& c2, float& c3,
                                        uint32_t a0, uint32_t a1, uint32_t a2, uint32_t a3,
                                        uint32_t b0, uint32_t b1) {
    asm volatile("mma.sync.aligned.m16n8k16.row.col.f32.f16.f16.f32 "
                 "{%0,%1,%2,%3}, {%4,%5,%6,%7}, {%8,%9}, {%0,%1,%2,%3};"
                 : "+f"(c0), "+f"(c1), "+f"(c2), "+f"(c3)
                 : "r"(a0), "r"(a1), "r"(a2), "r"(a3), "r"(b0), "r"(b1));
}
__device__ __forceinline__ void lds64(uint32_t& x, uint32_t& y, const void* p) {
    asm volatile("ld.shared.v2.b32 {%0,%1}, [%2];" : "=r"(x), "=r"(y) : "l"(__cvta_generic_to_shared(p)));
}
__device__ __forceinline__ void sts32(void* p, uint32_t v) {
    asm volatile("st.shared.b32 [%0], %1;" :: "l"(__cvta_generic_to_shared(p)), "r"(v));
}
// pair-permutation for fp32 tiles (hgemm): (j, j+4) adjacent
__device__ __forceinline__ int posk(int j) {
    return (j & 24) + ((j & 3) << 1) + ((j >> 2) & 1);
}
// half-tile word permutation (per 16-col chunk): word = chunk*8 + ((p&3)<<1|(p>>2))
__device__ __forceinline__ int halfword(int c) {
    int chunk = c >> 4, p = (c & 15) >> 1;
    return chunk * 8 + ((p & 3) << 1) + (p >> 2);
}

// ======================================================================
// Kernel 1: h = x @ W via mma.sync tf32, software-pipelined, with node
// projections + factorized exps fused into the epilogue (round-10 WIN),
// extended to also write g_el / g_er for the round-9 fused consumer.
// ======================================================================
__global__ __launch_bounds__(256) void k_hgemm(const float* __restrict__ x,
                                               const float* __restrict__ W,
                                               const float* __restrict__ al,
                                               const float* __restrict__ ar) {
    __shared__ float xs[2][32 * BSTR];
    __shared__ float Ws[2][32 * WSTR];

    int t = threadIdx.x, lane = t & 31, warp = t >> 5;
    int g = lane >> 2, ctg = lane & 3;
    int i0 = blockIdx.x * 32;
    int wm = warp >> 2, wn = warp & 3;
    int rmA = wm * 16 + g;
    int n0 = wn * 32;

    float acc[4][4];
#pragma unroll
    for (int nt = 0; nt < 4; nt++)
#pragma unroll
        for (int c = 0; c < 4; c++) acc[nt][c] = 0.0f;

    int xrow = t >> 3, xkq = (t & 7) * 4;
    const float* xp = &x[(size_t)(i0 + xrow) * DI + xkq];

    float4 xv;
    float4 wv[4];

#define HG_LDG(K0)                                                              \
    do {                                                                        \
        xv = *reinterpret_cast<const float4*>(xp + (K0));                       \
        _Pragma("unroll")                                                       \
        for (int r = 0; r < 4; r++) {                                           \
            int f = t + 256 * r;                                                \
            int kr = f >> 5, nc = (f & 31) * 4;                                 \
            wv[r] = *reinterpret_cast<const float4*>(&W[(size_t)((K0) + kr) * DO + nc]); \
        }                                                                       \
    } while (0)

#define HG_STS(S)                                                               \
    do {                                                                        \
        float* dst = &xs[S][xrow * BSTR];                                       \
        dst[posk(xkq + 0)] = __uint_as_float(cvt_tf32(xv.x));                   \
        dst[posk(xkq + 1)] = __uint_as_float(cvt_tf32(xv.y));                   \
        dst[posk(xkq + 2)] = __uint_as_float(cvt_tf32(xv.z));                   \
        dst[posk(xkq + 3)] = __uint_as_float(cvt_tf32(xv.w));                   \
        _Pragma("unroll")                                                       \
        for (int r = 0; r < 4; r++) {                                           \
            int f = t + 256 * r;                                                \
            int kr = f >> 5, nc = (f & 31) * 4;                                 \
            float* wd = &Ws[S][kr * WSTR + nc];                                 \
            wd[0] = __uint_as_float(cvt_tf32(wv[r].x));                         \
            wd[1] = __uint_as_float(cvt_tf32(wv[r].y));                         \
            wd[2] = __uint_as_float(cvt_tf32(wv[r].z));                         \
            wd[3] = __uint_as_float(cvt_tf32(wv[r].w));                         \
        }                                                                       \
    } while (0)

    HG_LDG(0);
    HG_STS(0);
    HG_LDG(32);

    const int NST = DI / 32;   // 16
    for (int it = 0; it < NST; ++it) {
        __syncthreads();
        if (it + 1 < NST) {
            HG_STS((it + 1) & 1);
            int nk = (it + 2 < NST) ? (it + 2) * 32 : 0;
            HG_LDG(nk);
        }
        const float* xsb = xs[it & 1];
        const float* Wsb = Ws[it & 1];
#pragma unroll
        for (int kk = 0; kk < 4; kk++) {
            uint32_t a0, a2, a1, a3;
            lds64(a0, a2, &xsb[rmA * BSTR + kk * 8 + ctg * 2]);
            lds64(a1, a3, &xsb[(rmA + 8) * BSTR + kk * 8 + ctg * 2]);
#pragma unroll
            for (int nt = 0; nt < 4; nt++) {
                int n = n0 + nt * 8 + g;
                uint32_t b0 = __float_as_uint(Wsb[(kk * 8 + ctg) * WSTR + n]);
                uint32_t b1 = __float_as_uint(Wsb[(kk * 8 + ctg + 4) * WSTR + n]);
                mma_tf32(acc[nt][0], acc[nt][1], acc[nt][2], acc[nt][3],
                         a0, a1, a2, a3, b0, b1);
            }
        }
    }
#undef HG_LDG
#undef HG_STS

    // ---- epilogue A: write g_hT (fp16) + stage h rows into smem ----
    float* hrow_s = &Ws[0][0];
    int lrA = rmA, lrB = rmA + 8;
    int rA = i0 + lrA, rB = i0 + lrB;
#pragma unroll
    for (int nt = 0; nt < 4; nt++) {
        int col = n0 + nt * 8 + ctg * 2;
        hrow_s[lrA * 132 + col]     = acc[nt][0];
        hrow_s[lrA * 132 + col + 1] = acc[nt][1];
        hrow_s[lrB * 132 + col]     = acc[nt][2];
        hrow_s[lrB * 132 + col + 1] = acc[nt][3];
        g_hT[(size_t)col * Nn + rA]       = __float2half_rn(acc[nt][0]);
        g_hT[(size_t)(col + 1) * Nn + rA] = __float2half_rn(acc[nt][1]);
        g_hT[(size_t)col * Nn + rB]       = __float2half_rn(acc[nt][2]);
        g_hT[(size_t)(col + 1) * Nn + rB] = __float2half_rn(acc[nt][3]);
    }
    __syncthreads();

    // ---- epilogue B: per-node projections + exps ----
    float alv[NH][4], arv[NH][4];
#pragma unroll
    for (int hd = 0; hd < NH; hd++)
#pragma unroll
        for (int k = 0; k < 4; k++) {
            alv[hd][k] = al[hd * DO + lane + 32 * k];
            arv[hd][k] = ar[hd * DO + lane + 32 * k];
        }
#pragma unroll
    for (int r = 0; r < 4; r++) {
        int row = warp * 4 + r;
        int node = i0 + row;
        float h0 = hrow_s[row * 132 + lane];
        float h1 = hrow_s[row * 132 + lane + 32];
        float h2 = hrow_s[row * 132 + lane + 64];
        float h3 = hrow_s[row * 132 + lane + 96];
#pragma unroll
        for (int hd = 0; hd < NH; hd++) {
            float sl = h0 * alv[hd][0] + h1 * alv[hd][1] + h2 * alv[hd][2] + h3 * alv[hd][3];
            float sr = h0 * arv[hd][0] + h1 * arv[hd][1] + h2 * arv[hd][2] + h3 * arv[hd][3];
#pragma unroll
            for (int off = 16; off; off >>= 1) {
                sl += __shfl_xor_sync(0xffffffffu, sl, off);
                sr += __shfl_xor_sync(0xffffffffu, sr, off);
            }
            if (lane == 0) {
                int idx = hd * Nn + node;
                g_el[idx] = sl;
                g_p[idx]  = expf(sl);
                g_p2[idx] = expf(0.2f * sl);
                g_er[idx] = sr;
                g_q[idx]  = expf(sr);
                g_q2[idx] = expf(0.2f * sr);
            }
        }
    }
}

// ======================================================================
// Kernel 2: fused masked-attention GEMM (round-9 WIN, verbatim).
// fp16 m16n8k16 mma, BM=128 / 512 thr / 128 CTAs / BK=32, single-barrier
// software pipeline, permuted half tiles (HSTR=48).
// ======================================================================
__global__ __launch_bounds__(512, 1) void k_fused(const float* __restrict__ adj,
                                                  const float* __restrict__ bias,
                                                  float* __restrict__ out) {
    extern __shared__ __half dsm[];    // [w0][w1][h0][h1], each TILEH halfs
    __shared__ float rowsum_s[BM];

    int t = threadIdx.x, lane = t & 31, warp = t >> 5;
    int g = lane >> 2, ctg = lane & 3;
    int head = blockIdx.x;
    int i0   = blockIdx.y * BM;
    int rm   = (warp >> 2) * 32;
    int n0   = (warp & 3) * 32;

    // i-side per-row constants (rows warp + 16*i)
    float eli[8], pi[8], p2i[8], rsum[8];
#pragma unroll
    for (int i = 0; i < 8; i++) {
        int idx = head * Nn + i0 + warp + 16 * i;
        eli[i] = g_el[idx]; pi[i] = g_p[idx]; p2i[i] = g_p2[idx];
        rsum[i] = 0.0f;
    }
    const float* adj_base = adj + (size_t)(i0 + warp) * Nn + lane;
    const float* er_base  = g_er + head * Nn + lane;
    const float* q_base   = g_q  + head * Nn + lane;
    const float* q2_base  = g_q2 + head * Nn + lane;
    int whalf = halfword(lane) * 2 + (lane & 1);   // weight STS half index
    int hn = t >> 2, hkq = (t & 3) * 8;            // h staging role
    int hword0 = (hkq >> 4) * 8 + ((hkq & 8) ? 1 : 0);
    const __half* hT_base = g_hT + (size_t)hn * Nn + hkq;

    float acc[2][4][4];
#pragma unroll
    for (int mt = 0; mt < 2; mt++)
#pragma unroll
        for (int nt = 0; nt < 4; nt++)
#pragma unroll
            for (int c = 0; c < 4; c++) acc[mt][nt][c] = 0.0f;

    float areg[8];
    uint4 hr;
    float erj, qj, q2j;

    // ---- prologue: regs(0) -> produce(0) into buf0 -> regs(1) ----
#pragma unroll
    for (int i = 0; i < 8; i++) areg[i] = adj_base[(size_t)(16 * i) * Nn];
    hr = *reinterpret_cast<const uint4*>(hT_base);
    erj = er_base[0]; qj = q_base[0]; q2j = q2_base[0];
    {
        __half* ws = dsm;
        __half* hs = dsm + 2 * TILEH;
        float pq[8], pq2[8];
#pragma unroll
        for (int i = 0; i < 8; i++) { pq[i] = pi[i] * qj; pq2[i] = p2i[i] * q2j; }
#pragma unroll
        for (int i = 0; i < 8; i++) {
            float sv = eli[i] + erj;
            float w = areg[i] * ((sv >= 0.0f) ? pq[i] : pq2[i]);
            __half wh = __float2half_rn(w);
            rsum[i] += __half2float(wh);
            ws[(warp + 16 * i) * HSTR + whalf] = wh;
        }
        __half* hd = &hs[hn * HSTR];
        sts32(hd + (hword0 + 0) * 2, hr.x);
        sts32(hd + (hword0 + 2) * 2, hr.y);
        sts32(hd + (hword0 + 4) * 2, hr.z);
        sts32(hd + (hword0 + 6) * 2, hr.w);
    }
#pragma unroll
    for (int i = 0; i < 8; i++) areg[i] = adj_base[(size_t)(16 * i) * Nn + BK];
    hr = *reinterpret_cast<const uint4*>(hT_base + BK);
    erj = er_base[BK]; qj = q_base[BK]; q2j = q2_base[BK];

    const int NIT = Nn / BK;
    for (int it = 0; it < NIT; ++it) {
        __syncthreads();   // produce(it) visible; mma(it-1) done everywhere

        // ---- produce(it+1) into other buffer (overlaps mma(it)) ----
        if (it + 1 < NIT) {
            __half* ws = dsm + ((it + 1) & 1) * TILEH;
            __half* hs = dsm + 2 * TILEH + ((it + 1) & 1) * TILEH;
            float pq[8], pq2[8];
#pragma unroll
            for (int i = 0; i < 8; i++) { pq[i] = pi[i] * qj; pq2[i] = p2i[i] * q2j; }
#pragma unroll
            for (int i = 0; i < 8; i++) {
                float sv = eli[i] + erj;
                float w = areg[i] * ((sv >= 0.0f) ? pq[i] : pq2[i]);
                __half wh = __float2half_rn(w);
                rsum[i] += __half2float(wh);
                ws[(warp + 16 * i) * HSTR + whalf] = wh;
            }
            __half* hd = &hs[hn * HSTR];
            sts32(hd + (hword0 + 0) * 2, hr.x);
            sts32(hd + (hword0 + 2) * 2, hr.y);
            sts32(hd + (hword0 + 4) * 2, hr.z);
            sts32(hd + (hword0 + 6) * 2, hr.w);
            // prefetch regs for stage it+2
            int nk0 = (it + 2 < NIT) ? (it + 2) * BK : 0;
#pragma unroll
            for (int i = 0; i < 8; i++) areg[i] = adj_base[(size_t)(16 * i) * Nn + nk0];
            hr = *reinterpret_cast<const uint4*>(hT_base + nk0);
            erj = er_base[nk0]; qj = q_base[nk0]; q2j = q2_base[nk0];
        }

        // ---- mma(it) on buffer it&1: 2 k16 chunks x 2 mt x 4 nt ----
        {
            const __half* ws = dsm + (it & 1) * TILEH;
            const __half* hs = dsm + 2 * TILEH + (it & 1) * TILEH;
#pragma unroll
            for (int kk = 0; kk < 2; kk++) {
                int koff = (kk * 8 + 2 * ctg) * 2;     // half offset of word pair
                uint32_t b0[4], b1[4];
#pragma unroll
                for (int nt = 0; nt < 4; nt++)
                    lds64(b0[nt], b1[nt], &hs[(n0 + nt * 8 + g) * HSTR + koff]);
#pragma unroll
                for (int mt = 0; mt < 2; mt++) {
                    uint32_t a0, a2, a1, a3;
                    lds64(a0, a2, &ws[(rm + mt * 16 + g) * HSTR + koff]);
                    lds64(a1, a3, &ws[(rm + mt * 16 + 8 + g) * HSTR + koff]);
#pragma unroll
                    for (int nt = 0; nt < 4; nt++)
                        mma_f16(acc[mt][nt][0], acc[mt][nt][1], acc[mt][nt][2], acc[mt][nt][3],
                                a0, a1, a2, a3, b0[nt], b1[nt]);
                }
            }
        }
    }

    // ---- rowsum reduce across lanes ----
#pragma unroll
    for (int i = 0; i < 8; i++) {
        float v = rsum[i];
#pragma unroll
        for (int off = 16; off; off >>= 1) v += __shfl_xor_sync(0xffffffffu, v, off);
        if (lane == 0) rowsum_s[warp + 16 * i] = v;
    }
    __syncthreads();

    // ---- epilogue: normalize + bias + store ----
#pragma unroll
    for (int mt = 0; mt < 2; mt++) {
        int lrA = rm + mt * 16 + g;
        int lrB = lrA + 8;
        float invA = 1.0f / fmaxf(rowsum_s[lrA], 1e-12f);
        float invB = 1.0f / fmaxf(rowsum_s[lrB], 1e-12f);
#pragma unroll
        for (int nt = 0; nt < 4; nt++) {
            int bcol = n0 + nt * 8 + ctg * 2;
            float2 bv = *reinterpret_cast<const float2*>(&bias[bcol]);
            float* opA = out + (size_t)(i0 + lrA) * (NH * DO) + head * DO + bcol;
            float* opB = out + (size_t)(i0 + lrB) * (NH * DO) + head * DO + bcol;
            *reinterpret_cast<float2*>(opA) =
                make_float2(acc[mt][nt][0] * invA + bv.x, acc[mt][nt][1] * invA + bv.y);
            *reinterpret_cast<float2*>(opB) =
                make_float2(acc[mt][nt][2] * invB + bv.x, acc[mt][nt][3] * invB + bv.y);
        }
    }
}

// ======================================================================
extern "C" void kernel_launch(void* const* d_in, const int* in_sizes, int n_in,
                              void* d_out, int out_size) {
    const float* adj = (const float*)d_in[0];
    const float* x   = (const float*)d_in[1];
    const float* W   = (const float*)d_in[2];
    const float* al  = (const float*)d_in[3];
    const float* ar  = (const float*)d_in[4];
    const float* b   = (const float*)d_in[5];
    float* out = (float*)d_out;

    const int dyn = 4 * TILEH * sizeof(__half);   // 49152 B
    cudaFuncSetAttribute(k_fused, cudaFuncAttributeMaxDynamicSharedMemorySize, dyn);

    k_hgemm<<<Nn / 32, 256>>>(x, W, al, ar);
    k_fused<<<dim3(NH, Nn / BM), 512, dyn>>>(adj, b, out);
}

// round 12
// speedup vs baseline: 1.0748x; 1.0176x over previous
#include <cuda_runtime.h>
#include <cuda_fp16.h>
#include <cstdint>

#define Nn 4096
#define DI 512
#define DO 128
#define NH 4
#define BM 128
#define BK 32
#define BSTR 36          // hgemm pair-permuted tile stride (floats)
#define WSTR 132         // hgemm W tile stride
#define HSTR 48          // fused tile row stride in halfs (96 B)
#define TILEH (BM * HSTR)  // 6144 halfs = 12 KB per tile

// ---------------- device scratch ----------------
__device__ __half g_hT[DO * Nn];   // h fp16, transposed [d][node] (B operand)
__device__ float g_el[NH * Nn], g_p[NH * Nn], g_p2[NH * Nn];
__device__ float g_er[NH * Nn], g_q[NH * Nn], g_q2[NH * Nn];

// ---------------- helpers ----------------
__device__ __forceinline__ uint32_t cvt_tf32(float x) {
    uint32_t r;
    asm("cvt.rna.tf32.f32 %0, %1;" : "=r"(r) : "f"(x));
    return r;
}
__device__ __forceinline__ void mma_tf32(float& c0, float& c1, float& c2, float& c3,
                                         uint32_t a0, uint32_t a1, uint32_t a2, uint32_t a3,
                                         uint32_t b0, uint32_t b1) {
    asm volatile("mma.sync.aligned.m16n8k8.row.col.f32.tf32.tf32.f32 "
                 "{%0,%1,%2,%3}, {%4,%5,%6,%7}, {%8,%9}, {%0,%1,%2,%3};"
                 : "+f"(c0), "+f"(c1), "+f"(c2), "+f"(c3)
                 : "r"(a0), "r"(a1), "r"(a2), "r"(a3), "r"(b0), "r"(b1));
}
__device__ __forceinline__ void mma_f16(float& c0, float& c1, float& c2, float& c3,
                                        uint32_t a0, uint32_t a1, uint32_t a2, uint32_t a3,
                                        uint32_t b0, uint32_t b1) {
    asm volatile("mma.sync.aligned.m16n8k16.row.col.f32.f16.f16.f32 "
                 "{%0,%1,%2,%3}, {%4,%5,%6,%7}, {%8,%9}, {%0,%1,%2,%3};"
                 : "+f"(c0), "+f"(c1), "+f"(c2), "+f"(c3)
                 : "r"(a0), "r"(a1), "r"(a2), "r"(a3), "r"(b0), "r"(b1));
}
__device__ __forceinline__ void lds64(uint32_t& x, uint32_t& y, const void* p) {
    asm volatile("ld.shared.v2.b32 {%0,%1}, [%2];" : "=r"(x), "=r"(y) : "l"(__cvta_generic_to_shared(p)));
}
__device__ __forceinline__ void sts32(void* p, uint32_t v) {
    asm volatile("st.shared.b32 [%0], %1;" :: "l"(__cvta_generic_to_shared(p)), "r"(v));
}
// pair-permutation for fp32 tiles (hgemm): (j, j+4) adjacent
__device__ __forceinline__ int posk(int j) {
    return (j & 24) + ((j & 3) << 1) + ((j >> 2) & 1);
}
// half-tile word permutation (per 16-col chunk): word = chunk*8 + ((p&3)<<1|(p>>2))
__device__ __forceinline__ int halfword(int c) {
    int chunk = c >> 4, p = (c & 15) >> 1;
    return chunk * 8 + ((p & 3) << 1) + (p >> 2);
}
// word index for j-pair p (j = 2p, 2p+1), p in 0..15
__device__ __forceinline__ int pairword(int p) {
    int pin = p & 7;
    return (p >> 3) * 8 + ((pin & 3) << 1) + (pin >> 2);
}

// ======================================================================
// Kernel 1: h = x @ W via mma.sync tf32, software-pipelined, with node
// projections + factorized exps fused into the epilogue (round-11 best).
// ======================================================================
__global__ __launch_bounds__(256) void k_hgemm(const float* __restrict__ x,
                                               const float* __restrict__ W,
                                               const float* __restrict__ al,
                                               const float* __restrict__ ar) {
    __shared__ float xs[2][32 * BSTR];
    __shared__ float Ws[2][32 * WSTR];

    int t = threadIdx.x, lane = t & 31, warp = t >> 5;
    int g = lane >> 2, ctg = lane & 3;
    int i0 = blockIdx.x * 32;
    int wm = warp >> 2, wn = warp & 3;
    int rmA = wm * 16 + g;
    int n0 = wn * 32;

    float acc[4][4];
#pragma unroll
    for (int nt = 0; nt < 4; nt++)
#pragma unroll
        for (int c = 0; c < 4; c++) acc[nt][c] = 0.0f;

    int xrow = t >> 3, xkq = (t & 7) * 4;
    const float* xp = &x[(size_t)(i0 + xrow) * DI + xkq];

    float4 xv;
    float4 wv[4];

#define HG_LDG(K0)                                                              \
    do {                                                                        \
        xv = *reinterpret_cast<const float4*>(xp + (K0));                       \
        _Pragma("unroll")                                                       \
        for (int r = 0; r < 4; r++) {                                           \
            int f = t + 256 * r;                                                \
            int kr = f >> 5, nc = (f & 31) * 4;                                 \
            wv[r] = *reinterpret_cast<const float4*>(&W[(size_t)((K0) + kr) * DO + nc]); \
        }                                                                       \
    } while (0)

#define HG_STS(S)                                                               \
    do {                                                                        \
        float* dst = &xs[S][xrow * BSTR];                                       \
        dst[posk(xkq + 0)] = __uint_as_float(cvt_tf32(xv.x));                   \
        dst[posk(xkq + 1)] = __uint_as_float(cvt_tf32(xv.y));                   \
        dst[posk(xkq + 2)] = __uint_as_float(cvt_tf32(xv.z));                   \
        dst[posk(xkq + 3)] = __uint_as_float(cvt_tf32(xv.w));                   \
        _Pragma("unroll")                                                       \
        for (int r = 0; r < 4; r++) {                                           \
            int f = t + 256 * r;                                                \
            int kr = f >> 5, nc = (f & 31) * 4;                                 \
            float* wd = &Ws[S][kr * WSTR + nc];                                 \
            wd[0] = __uint_as_float(cvt_tf32(wv[r].x));                         \
            wd[1] = __uint_as_float(cvt_tf32(wv[r].y));                         \
            wd[2] = __uint_as_float(cvt_tf32(wv[r].z));                         \
            wd[3] = __uint_as_float(cvt_tf32(wv[r].w));                         \
        }                                                                       \
    } while (0)

    HG_LDG(0);
    HG_STS(0);
    HG_LDG(32);

    const int NST = DI / 32;   // 16
    for (int it = 0; it < NST; ++it) {
        __syncthreads();
        if (it + 1 < NST) {
            HG_STS((it + 1) & 1);
            int nk = (it + 2 < NST) ? (it + 2) * 32 : 0;
            HG_LDG(nk);
        }
        const float* xsb = xs[it & 1];
        const float* Wsb = Ws[it & 1];
#pragma unroll
        for (int kk = 0; kk < 4; kk++) {
            uint32_t a0, a2, a1, a3;
            lds64(a0, a2, &xsb[rmA * BSTR + kk * 8 + ctg * 2]);
            lds64(a1, a3, &xsb[(rmA + 8) * BSTR + kk * 8 + ctg * 2]);
#pragma unroll
            for (int nt = 0; nt < 4; nt++) {
                int n = n0 + nt * 8 + g;
                uint32_t b0 = __float_as_uint(Wsb[(kk * 8 + ctg) * WSTR + n]);
                uint32_t b1 = __float_as_uint(Wsb[(kk * 8 + ctg + 4) * WSTR + n]);
                mma_tf32(acc[nt][0], acc[nt][1], acc[nt][2], acc[nt][3],
                         a0, a1, a2, a3, b0, b1);
            }
        }
    }
#undef HG_LDG
#undef HG_STS

    // ---- epilogue A: write g_hT (fp16) + stage h rows into smem ----
    float* hrow_s = &Ws[0][0];
    int lrA = rmA, lrB = rmA + 8;
    int rA = i0 + lrA, rB = i0 + lrB;
#pragma unroll
    for (int nt = 0; nt < 4; nt++) {
        int col = n0 + nt * 8 + ctg * 2;
        hrow_s[lrA * 132 + col]     = acc[nt][0];
        hrow_s[lrA * 132 + col + 1] = acc[nt][1];
        hrow_s[lrB * 132 + col]     = acc[nt][2];
        hrow_s[lrB * 132 + col + 1] = acc[nt][3];
        g_hT[(size_t)col * Nn + rA]       = __float2half_rn(acc[nt][0]);
        g_hT[(size_t)(col + 1) * Nn + rA] = __float2half_rn(acc[nt][1]);
        g_hT[(size_t)col * Nn + rB]       = __float2half_rn(acc[nt][2]);
        g_hT[(size_t)(col + 1) * Nn + rB] = __float2half_rn(acc[nt][3]);
    }
    __syncthreads();

    // ---- epilogue B: per-node projections + exps ----
    float alv[NH][4], arv[NH][4];
#pragma unroll
    for (int hd = 0; hd < NH; hd++)
#pragma unroll
        for (int k = 0; k < 4; k++) {
            alv[hd][k] = al[hd * DO + lane + 32 * k];
            arv[hd][k] = ar[hd * DO + lane + 32 * k];
        }
#pragma unroll
    for (int r = 0; r < 4; r++) {
        int row = warp * 4 + r;
        int node = i0 + row;
        float h0 = hrow_s[row * 132 + lane];
        float h1 = hrow_s[row * 132 + lane + 32];
        float h2 = hrow_s[row * 132 + lane + 64];
        float h3 = hrow_s[row * 132 + lane + 96];
#pragma unroll
        for (int hd = 0; hd < NH; hd++) {
            float sl = h0 * alv[hd][0] + h1 * alv[hd][1] + h2 * alv[hd][2] + h3 * alv[hd][3];
            float sr = h0 * arv[hd][0] + h1 * arv[hd][1] + h2 * arv[hd][2] + h3 * arv[hd][3];
#pragma unroll
            for (int off = 16; off; off >>= 1) {
                sl += __shfl_xor_sync(0xffffffffu, sl, off);
                sr += __shfl_xor_sync(0xffffffffu, sr, off);
            }
            if (lane == 0) {
                int idx = hd * Nn + node;
                g_el[idx] = sl;
                g_p[idx]  = expf(sl);
                g_p2[idx] = expf(0.2f * sl);
                g_er[idx] = sr;
                g_q[idx]  = expf(sr);
                g_q2[idx] = expf(0.2f * sr);
            }
        }
    }
}

// ======================================================================
// Kernel 2: fused masked-attention GEMM. Round-11 structure with the
// producer remapped to (4 i-rows x 2 adjacent j) per thread: LDG.64 adj,
// STS.32 half2 weight stores (conflict-free: paired rows differ by 2 ->
// +16 bank shift), packed cvt. mma phase UNCHANGED.
// ======================================================================
__global__ __launch_bounds__(512, 1) void k_fused(const float* __restrict__ adj,
                                                  const float* __restrict__ bias,
                                                  float* __restrict__ out) {
    extern __shared__ __half dsm[];    // [w0][w1][h0][h1], each TILEH halfs
    __shared__ float rowsum_s[BM];

    int t = threadIdx.x, lane = t & 31, warp = t >> 5;
    int g = lane >> 2, ctg = lane & 3;
    int head = blockIdx.x;
    int i0   = blockIdx.y * BM;
    int rm   = (warp >> 2) * 32;
    int n0   = (warp & 3) * 32;

    // ---- producer role: h-group + j-pair ----
    int ph = lane >> 4;            // 0/1: row-parity group
    int pp = lane & 15;            // j-pair index: j = 2*pp, 2*pp+1
    int prow[4];                   // rows: 8*warp + 2*ph + {0,1,4,5}
    prow[0] = 8 * warp + 2 * ph;
    prow[1] = prow[0] + 1;
    prow[2] = prow[0] + 4;
    prow[3] = prow[0] + 5;
    int pword = pairword(pp);      // word slot for this j-pair

    // i-side per-row constants (4 rows)
    float eli[4], pi[4], p2i[4], rsum[4];
#pragma unroll
    for (int i = 0; i < 4; i++) {
        int idx = head * Nn + i0 + prow[i];
        eli[i] = g_el[idx]; pi[i] = g_p[idx]; p2i[i] = g_p2[idx];
        rsum[i] = 0.0f;
    }
    const float* adj_p0 = adj + (size_t)(i0 + prow[0]) * Nn + 2 * pp;
    const float* adj_p1 = adj + (size_t)(i0 + prow[1]) * Nn + 2 * pp;
    const float* adj_p2 = adj + (size_t)(i0 + prow[2]) * Nn + 2 * pp;
    const float* adj_p3 = adj + (size_t)(i0 + prow[3]) * Nn + 2 * pp;
    const float* er_b  = g_er + head * Nn + 2 * pp;
    const float* q_b   = g_q  + head * Nn + 2 * pp;
    const float* q2_b  = g_q2 + head * Nn + 2 * pp;

    int hn = t >> 2, hkq = (t & 3) * 8;            // h staging role (unchanged)
    int hword0 = (hkq >> 4) * 8 + ((hkq & 8) ? 1 : 0);
    const __half* hT_base = g_hT + (size_t)hn * Nn + hkq;

    float acc[2][4][4];
#pragma unroll
    for (int mt = 0; mt < 2; mt++)
#pragma unroll
        for (int nt = 0; nt < 4; nt++)
#pragma unroll
            for (int c = 0; c < 4; c++) acc[mt][nt][c] = 0.0f;

    float2 areg[4];
    uint4 hr;
    float2 er2, qj2, q2j2;

#define FU_LDG(K0)                                                            \
    do {                                                                      \
        areg[0] = *reinterpret_cast<const float2*>(adj_p0 + (K0));            \
        areg[1] = *reinterpret_cast<const float2*>(adj_p1 + (K0));            \
        areg[2] = *reinterpret_cast<const float2*>(adj_p2 + (K0));            \
        areg[3] = *reinterpret_cast<const float2*>(adj_p3 + (K0));            \
        hr = *reinterpret_cast<const uint4*>(hT_base + (K0));                 \
        er2  = *reinterpret_cast<const float2*>(er_b + (K0));                 \
        qj2  = *reinterpret_cast<const float2*>(q_b + (K0));                  \
        q2j2 = *reinterpret_cast<const float2*>(q2_b + (K0));                 \
    } while (0)

#define FU_PROD(S)                                                            \
    do {                                                                      \
        __half* ws = dsm + (S) * TILEH;                                       \
        __half* hs = dsm + 2 * TILEH + (S) * TILEH;                           \
        _Pragma("unroll")                                                     \
        for (int i = 0; i < 4; i++) {                                         \
            float sva = eli[i] + er2.x;                                       \
            float wa = areg[i].x * ((sva >= 0.0f) ? (pi[i] * qj2.x)           \
                                                  : (p2i[i] * q2j2.x));       \
            float svb = eli[i] + er2.y;                                       \
            float wb = areg[i].y * ((svb >= 0.0f) ? (pi[i] * qj2.y)           \
                                                  : (p2i[i] * q2j2.y));       \
            __half2 wh2 = __floats2half2_rn(wa, wb);                          \
            rsum[i] += __low2float(wh2) + __high2float(wh2);                  \
            sts32(&ws[prow[i] * HSTR + 2 * pword],                            \
                  *reinterpret_cast<uint32_t*>(&wh2));                        \
        }                                                                     \
        __half* hd = &hs[hn * HSTR];                                          \
        sts32(hd + (hword0 + 0) * 2, hr.x);                                   \
        sts32(hd + (hword0 + 2) * 2, hr.y);                                   \
        sts32(hd + (hword0 + 4) * 2, hr.z);                                   \
        sts32(hd + (hword0 + 6) * 2, hr.w);                                   \
    } while (0)

    // ---- prologue: regs(0) -> produce(0) into buf0 -> regs(1) ----
    FU_LDG(0);
    FU_PROD(0);
    FU_LDG(BK);

    const int NIT = Nn / BK;
    for (int it = 0; it < NIT; ++it) {
        __syncthreads();   // produce(it) visible; mma(it-1) done everywhere

        // ---- produce(it+1) into other buffer (overlaps mma(it)) ----
        if (it + 1 < NIT) {
            FU_PROD((it + 1) & 1);
            int nk0 = (it + 2 < NIT) ? (it + 2) * BK : 0;
            FU_LDG(nk0);
        }

        // ---- mma(it) on buffer it&1: 2 k16 chunks x 2 mt x 4 nt ----
        {
            const __half* ws = dsm + (it & 1) * TILEH;
            const __half* hs = dsm + 2 * TILEH + (it & 1) * TILEH;
#pragma unroll
            for (int kk = 0; kk < 2; kk++) {
                int koff = (kk * 8 + 2 * ctg) * 2;     // half offset of word pair
                uint32_t b0[4], b1[4];
#pragma unroll
                for (int nt = 0; nt < 4; nt++)
                    lds64(b0[nt], b1[nt], &hs[(n0 + nt * 8 + g) * HSTR + koff]);
#pragma unroll
                for (int mt = 0; mt < 2; mt++) {
                    uint32_t a0, a2, a1, a3;
                    lds64(a0, a2, &ws[(rm + mt * 16 + g) * HSTR + koff]);
                    lds64(a1, a3, &ws[(rm + mt * 16 + 8 + g) * HSTR + koff]);
#pragma unroll
                    for (int nt = 0; nt < 4; nt++)
                        mma_f16(acc[mt][nt][0], acc[mt][nt][1], acc[mt][nt][2], acc[mt][nt][3],
                                a0, a1, a2, a3, b0[nt], b1[nt]);
                }
            }
        }
    }
#undef FU_LDG
#undef FU_PROD

    // ---- rowsum reduce within 16-lane h-groups (each row's 32 j live
    //      on 16 lanes of one group, 2 j per lane) ----
#pragma unroll
    for (int i = 0; i < 4; i++) {
        float v = rsum[i];
#pragma unroll
        for (int off = 8; off; off >>= 1) v += __shfl_xor_sync(0xffffffffu, v, off);
        if (pp == 0) rowsum_s[prow[i]] = v;
    }
    __syncthreads();

    // ---- epilogue: normalize + bias + store ----
#pragma unroll
    for (int mt = 0; mt < 2; mt++) {
        int lrA = rm + mt * 16 + g;
        int lrB = lrA + 8;
        float invA = 1.0f / fmaxf(rowsum_s[lrA], 1e-12f);
        float invB = 1.0f / fmaxf(rowsum_s[lrB], 1e-12f);
#pragma unroll
        for (int nt = 0; nt < 4; nt++) {
            int bcol = n0 + nt * 8 + ctg * 2;
            float2 bv = *reinterpret_cast<const float2*>(&bias[bcol]);
            float* opA = out + (size_t)(i0 + lrA) * (NH * DO) + head * DO + bcol;
            float* opB = out + (size_t)(i0 + lrB) * (NH * DO) + head * DO + bcol;
            *reinterpret_cast<float2*>(opA) =
                make_float2(acc[mt][nt][0] * invA + bv.x, acc[mt][nt][1] * invA + bv.y);
            *reinterpret_cast<float2*>(opB) =
                make_float2(acc[mt][nt][2] * invB + bv.x, acc[mt][nt][3] * invB + bv.y);
        }
    }
}

// ======================================================================
extern "C" void kernel_launch(void* const* d_in, const int* in_sizes, int n_in,
                              void* d_out, int out_size) {
    const float* adj = (const float*)d_in[0];
    const float* x   = (const float*)d_in[1];
    const float* W   = (const float*)d_in[2];
    const float* al  = (const float*)d_in[3];
    const float* ar  = (const float*)d_in[4];
    const float* b   = (const float*)d_in[5];
    float* out = (float*)d_out;

    const int dyn = 4 * TILEH * sizeof(__half);   // 49152 B
    cudaFuncSetAttribute(k_fused, cudaFuncAttributeMaxDynamicSharedMemorySize, dyn);

    k_hgemm<<<Nn / 32, 256>>>(x, W, al, ar);
    k_fused<<<dim3(NH, Nn / BM), 512, dyn>>>(adj, b, out);
}

// round 13
// speedup vs baseline: 1.1897x; 1.1070x over previous
#include <cuda_runtime.h>
#include <cuda_fp16.h>
#include <cstdint>

#define Nn 4096
#define DI 512
#define DO 128
#define NH 4
#define BM 128
#define BK 32
#define BSTR 36          // hgemm pair-permuted tile stride (floats)
#define WSTR 132         // hgemm W tile stride
#define HSTR 48          // fused tile row stride in halfs (96 B)
#define TILEH (BM * HSTR)  // 6144 halfs = 12 KB per tile

// ---------------- device scratch ----------------
__device__ __half g_hT[DO * Nn];   // h fp16, transposed [d][node] (B operand)
__device__ float g_p[NH * Nn], g_p2[NH * Nn];   // exp(el), exp(0.2 el)
__device__ float g_q[NH * Nn], g_q2[NH * Nn];   // exp(er), exp(0.2 er)

// ---------------- helpers ----------------
__device__ __forceinline__ uint32_t cvt_tf32(float x) {
    uint32_t r;
    asm("cvt.rna.tf32.f32 %0, %1;" : "=r"(r) : "f"(x));
    return r;
}
__device__ __forceinline__ void mma_tf32(float& c0, float& c1, float& c2, float& c3,
                                         uint32_t a0, uint32_t a1, uint32_t a2, uint32_t a3,
                                         uint32_t b0, uint32_t b1) {
    asm volatile("mma.sync.aligned.m16n8k8.row.col.f32.tf32.tf32.f32 "
                 "{%0,%1,%2,%3}, {%4,%5,%6,%7}, {%8,%9}, {%0,%1,%2,%3};"
                 : "+f"(c0), "+f"(c1), "+f"(c2), "+f"(c3)
                 : "r"(a0), "r"(a1), "r"(a2), "r"(a3), "r"(b0), "r"(b1));
}
__device__ __forceinline__ void mma_f16(float& c0, float& c1, float& c2, float& c3,
                                        uint32_t a0, uint32_t a1, uint32_t a2, uint32_t a3,
                                        uint32_t b0, uint32_t b1) {
    asm volatile("mma.sync.aligned.m16n8k16.row.col.f32.f16.f16.f32 "
                 "{%0,%1,%2,%3}, {%4,%5,%6,%7}, {%8,%9}, {%0,%1,%2,%3};"
                 : "+f"(c0), "+f"(c1), "+f"(c2), "+f"(c3)
                 : "r"(a0), "r"(a1), "r"(a2), "r"(a3), "r"(b0), "r"(b1));
}
__device__ __forceinline__ void lds64(uint32_t& x, uint32_t& y, const void* p) {
    asm volatile("ld.shared.v2.b32 {%0,%1}, [%2];" : "=r"(x), "=r"(y) : "l"(__cvta_generic_to_shared(p)));
}
__device__ __forceinline__ void sts32(void* p, uint32_t v) {
    asm volatile("st.shared.b32 [%0], %1;" :: "l"(__cvta_generic_to_shared(p)), "r"(v));
}
// pair-permutation for fp32 tiles (hgemm): (j, j+4) adjacent
__device__ __forceinline__ int posk(int j) {
    return (j & 24) + ((j & 3) << 1) + ((j >> 2) & 1);
}
// word index for j-pair p (j = 2p, 2p+1), p in 0..15
__device__ __forceinline__ int pairword(int p) {
    int pin = p & 7;
    return (p >> 3) * 8 + ((pin & 3) << 1) + (pin >> 2);
}

// ======================================================================
// Kernel 1: h = x @ W via mma.sync tf32, software-pipelined, with node
// projections + factorized exps fused into the epilogue.
// (el/er raw values no longer needed by the consumer -> not stored.)
// ======================================================================
__global__ __launch_bounds__(256) void k_hgemm(const float* __restrict__ x,
                                               const float* __restrict__ W,
                                               const float* __restrict__ al,
                                               const float* __restrict__ ar) {
    __shared__ float xs[2][32 * BSTR];
    __shared__ float Ws[2][32 * WSTR];

    int t = threadIdx.x, lane = t & 31, warp = t >> 5;
    int g = lane >> 2, ctg = lane & 3;
    int i0 = blockIdx.x * 32;
    int wm = warp >> 2, wn = warp & 3;
    int rmA = wm * 16 + g;
    int n0 = wn * 32;

    float acc[4][4];
#pragma unroll
    for (int nt = 0; nt < 4; nt++)
#pragma unroll
        for (int c = 0; c < 4; c++) acc[nt][c] = 0.0f;

    int xrow = t >> 3, xkq = (t & 7) * 4;
    const float* xp = &x[(size_t)(i0 + xrow) * DI + xkq];

    float4 xv;
    float4 wv[4];

#define HG_LDG(K0)                                                              \
    do {                                                                        \
        xv = *reinterpret_cast<const float4*>(xp + (K0));                       \
        _Pragma("unroll")                                                       \
        for (int r = 0; r < 4; r++) {                                           \
            int f = t + 256 * r;                                                \
            int kr = f >> 5, nc = (f & 31) * 4;                                 \
            wv[r] = *reinterpret_cast<const float4*>(&W[(size_t)((K0) + kr) * DO + nc]); \
        }                                                                       \
    } while (0)

#define HG_STS(S)                                                               \
    do {                                                                        \
        float* dst = &xs[S][xrow * BSTR];                                       \
        dst[posk(xkq + 0)] = __uint_as_float(cvt_tf32(xv.x));                   \
        dst[posk(xkq + 1)] = __uint_as_float(cvt_tf32(xv.y));                   \
        dst[posk(xkq + 2)] = __uint_as_float(cvt_tf32(xv.z));                   \
        dst[posk(xkq + 3)] = __uint_as_float(cvt_tf32(xv.w));                   \
        _Pragma("unroll")                                                       \
        for (int r = 0; r < 4; r++) {                                           \
            int f = t + 256 * r;                                                \
            int kr = f >> 5, nc = (f & 31) * 4;                                 \
            float* wd = &Ws[S][kr * WSTR + nc];                                 \
            wd[0] = __uint_as_float(cvt_tf32(wv[r].x));                         \
            wd[1] = __uint_as_float(cvt_tf32(wv[r].y));                         \
            wd[2] = __uint_as_float(cvt_tf32(wv[r].z));                         \
            wd[3] = __uint_as_float(cvt_tf32(wv[r].w));                         \
        }                                                                       \
    } while (0)

    HG_LDG(0);
    HG_STS(0);
    HG_LDG(32);

    const int NST = DI / 32;   // 16
    for (int it = 0; it < NST; ++it) {
        __syncthreads();
        if (it + 1 < NST) {
            HG_STS((it + 1) & 1);
            int nk = (it + 2 < NST) ? (it + 2) * 32 : 0;
            HG_LDG(nk);
        }
        const float* xsb = xs[it & 1];
        const float* Wsb = Ws[it & 1];
#pragma unroll
        for (int kk = 0; kk < 4; kk++) {
            uint32_t a0, a2, a1, a3;
            lds64(a0, a2, &xsb[rmA * BSTR + kk * 8 + ctg * 2]);
            lds64(a1, a3, &xsb[(rmA + 8) * BSTR + kk * 8 + ctg * 2]);
#pragma unroll
            for (int nt = 0; nt < 4; nt++) {
                int n = n0 + nt * 8 + g;
                uint32_t b0 = __float_as_uint(Wsb[(kk * 8 + ctg) * WSTR + n]);
                uint32_t b1 = __float_as_uint(Wsb[(kk * 8 + ctg + 4) * WSTR + n]);
                mma_tf32(acc[nt][0], acc[nt][1], acc[nt][2], acc[nt][3],
                         a0, a1, a2, a3, b0, b1);
            }
        }
    }
#undef HG_LDG
#undef HG_STS

    // ---- epilogue A: write g_hT (fp16) + stage h rows into smem ----
    float* hrow_s = &Ws[0][0];
    int lrA = rmA, lrB = rmA + 8;
    int rA = i0 + lrA, rB = i0 + lrB;
#pragma unroll
    for (int nt = 0; nt < 4; nt++) {
        int col = n0 + nt * 8 + ctg * 2;
        hrow_s[lrA * 132 + col]     = acc[nt][0];
        hrow_s[lrA * 132 + col + 1] = acc[nt][1];
        hrow_s[lrB * 132 + col]     = acc[nt][2];
        hrow_s[lrB * 132 + col + 1] = acc[nt][3];
        g_hT[(size_t)col * Nn + rA]       = __float2half_rn(acc[nt][0]);
        g_hT[(size_t)(col + 1) * Nn + rA] = __float2half_rn(acc[nt][1]);
        g_hT[(size_t)col * Nn + rB]       = __float2half_rn(acc[nt][2]);
        g_hT[(size_t)(col + 1) * Nn + rB] = __float2half_rn(acc[nt][3]);
    }
    __syncthreads();

    // ---- epilogue B: per-node projections + exps ----
    float alv[NH][4], arv[NH][4];
#pragma unroll
    for (int hd = 0; hd < NH; hd++)
#pragma unroll
        for (int k = 0; k < 4; k++) {
            alv[hd][k] = al[hd * DO + lane + 32 * k];
            arv[hd][k] = ar[hd * DO + lane + 32 * k];
        }
#pragma unroll
    for (int r = 0; r < 4; r++) {
        int row = warp * 4 + r;
        int node = i0 + row;
        float h0 = hrow_s[row * 132 + lane];
        float h1 = hrow_s[row * 132 + lane + 32];
        float h2 = hrow_s[row * 132 + lane + 64];
        float h3 = hrow_s[row * 132 + lane + 96];
#pragma unroll
        for (int hd = 0; hd < NH; hd++) {
            float sl = h0 * alv[hd][0] + h1 * alv[hd][1] + h2 * alv[hd][2] + h3 * alv[hd][3];
            float sr = h0 * arv[hd][0] + h1 * arv[hd][1] + h2 * arv[hd][2] + h3 * arv[hd][3];
#pragma unroll
            for (int off = 16; off; off >>= 1) {
                sl += __shfl_xor_sync(0xffffffffu, sl, off);
                sr += __shfl_xor_sync(0xffffffffu, sr, off);
            }
            if (lane == 0) {
                int idx = hd * Nn + node;
                g_p[idx]  = expf(sl);
                g_p2[idx] = expf(0.2f * sl);
                g_q[idx]  = expf(sr);
                g_q2[idx] = expf(0.2f * sr);
            }
        }
    }
}

// ======================================================================
// Kernel 2: fused masked-attention GEMM. Round-12 structure; the producer
// branch select is replaced by the algebraic identity
//   (el+er>=0 ? e^{el}e^{er} : e^{.2el}e^{.2er}) == max(p_i q_j, p2_i q2_j)
// (exp monotonic; s >= 0.2s iff s >= 0). Drops FSETP/SEL chains, the
// el/er loads, and the half2 unpack in rowsum. mma phase UNCHANGED.
// ======================================================================
__global__ __launch_bounds__(512, 1) void k_fused(const float* __restrict__ adj,
                                                  const float* __restrict__ bias,
                                                  float* __restrict__ out) {
    extern __shared__ __half dsm[];    // [w0][w1][h0][h1], each TILEH halfs
    __shared__ float rowsum_s[BM];

    int t = threadIdx.x, lane = t & 31, warp = t >> 5;
    int g = lane >> 2, ctg = lane & 3;
    int head = blockIdx.x;
    int i0   = blockIdx.y * BM;
    int rm   = (warp >> 2) * 32;
    int n0   = (warp & 3) * 32;

    // ---- producer role: h-group + j-pair ----
    int ph = lane >> 4;            // 0/1: row-parity group
    int pp = lane & 15;            // j-pair index: j = 2*pp, 2*pp+1
    int prow[4];                   // rows: 8*warp + 2*ph + {0,1,4,5}
    prow[0] = 8 * warp + 2 * ph;
    prow[1] = prow[0] + 1;
    prow[2] = prow[0] + 4;
    prow[3] = prow[0] + 5;
    int pword = pairword(pp);      // word slot for this j-pair

    // i-side per-row constants (4 rows)
    float pi[4], p2i[4], rsum[4];
#pragma unroll
    for (int i = 0; i < 4; i++) {
        int idx = head * Nn + i0 + prow[i];
        pi[i] = g_p[idx]; p2i[i] = g_p2[idx];
        rsum[i] = 0.0f;
    }
    const float* adj_p0 = adj + (size_t)(i0 + prow[0]) * Nn + 2 * pp;
    const float* adj_p1 = adj + (size_t)(i0 + prow[1]) * Nn + 2 * pp;
    const float* adj_p2 = adj + (size_t)(i0 + prow[2]) * Nn + 2 * pp;
    const float* adj_p3 = adj + (size_t)(i0 + prow[3]) * Nn + 2 * pp;
    const float* q_b   = g_q  + head * Nn + 2 * pp;
    const float* q2_b  = g_q2 + head * Nn + 2 * pp;

    int hn = t >> 2, hkq = (t & 3) * 8;            // h staging role (unchanged)
    int hword0 = (hkq >> 4) * 8 + ((hkq & 8) ? 1 : 0);
    const __half* hT_base = g_hT + (size_t)hn * Nn + hkq;

    float acc[2][4][4];
#pragma unroll
    for (int mt = 0; mt < 2; mt++)
#pragma unroll
        for (int nt = 0; nt < 4; nt++)
#pragma unroll
            for (int c = 0; c < 4; c++) acc[mt][nt][c] = 0.0f;

    float2 areg[4];
    uint4 hr;
    float2 qj2, q2j2;

#define FU_LDG(K0)                                                            \
    do {                                                                      \
        areg[0] = *reinterpret_cast<const float2*>(adj_p0 + (K0));            \
        areg[1] = *reinterpret_cast<const float2*>(adj_p1 + (K0));            \
        areg[2] = *reinterpret_cast<const float2*>(adj_p2 + (K0));            \
        areg[3] = *reinterpret_cast<const float2*>(adj_p3 + (K0));            \
        hr = *reinterpret_cast<const uint4*>(hT_base + (K0));                 \
        qj2  = *reinterpret_cast<const float2*>(q_b + (K0));                  \
        q2j2 = *reinterpret_cast<const float2*>(q2_b + (K0));                 \
    } while (0)

#define FU_PROD(S)                                                            \
    do {                                                                      \
        __half* ws = dsm + (S) * TILEH;                                       \
        __half* hs = dsm + 2 * TILEH + (S) * TILEH;                           \
        _Pragma("unroll")                                                     \
        for (int i = 0; i < 4; i++) {                                         \
            float wa = areg[i].x * fmaxf(pi[i] * qj2.x, p2i[i] * q2j2.x);     \
            float wb = areg[i].y * fmaxf(pi[i] * qj2.y, p2i[i] * q2j2.y);     \
            __half2 wh2 = __floats2half2_rn(wa, wb);                          \
            rsum[i] += wa + wb;                                               \
            sts32(&ws[prow[i] * HSTR + 2 * pword],                            \
                  *reinterpret_cast<uint32_t*>(&wh2));                        \
        }                                                                     \
        __half* hd = &hs[hn * HSTR];                                          \
        sts32(hd + (hword0 + 0) * 2, hr.x);                                   \
        sts32(hd + (hword0 + 2) * 2, hr.y);                                   \
        sts32(hd + (hword0 + 4) * 2, hr.z);                                   \
        sts32(hd + (hword0 + 6) * 2, hr.w);                                   \
    } while (0)

    // ---- prologue: regs(0) -> produce(0) into buf0 -> regs(1) ----
    FU_LDG(0);
    FU_PROD(0);
    FU_LDG(BK);

    const int NIT = Nn / BK;
    for (int it = 0; it < NIT; ++it) {
        __syncthreads();   // produce(it) visible; mma(it-1) done everywhere

        // ---- produce(it+1) into other buffer (overlaps mma(it)) ----
        if (it + 1 < NIT) {
            FU_PROD((it + 1) & 1);
            int nk0 = (it + 2 < NIT) ? (it + 2) * BK : 0;
            FU_LDG(nk0);
        }

        // ---- mma(it) on buffer it&1: 2 k16 chunks x 2 mt x 4 nt ----
        {
            const __half* ws = dsm + (it & 1) * TILEH;
            const __half* hs = dsm + 2 * TILEH + (it & 1) * TILEH;
#pragma unroll
            for (int kk = 0; kk < 2; kk++) {
                int koff = (kk * 8 + 2 * ctg) * 2;     // half offset of word pair
                uint32_t b0[4], b1[4];
#pragma unroll
                for (int nt = 0; nt < 4; nt++)
                    lds64(b0[nt], b1[nt], &hs[(n0 + nt * 8 + g) * HSTR + koff]);
#pragma unroll
                for (int mt = 0; mt < 2; mt++) {
                    uint32_t a0, a2, a1, a3;
                    lds64(a0, a2, &ws[(rm + mt * 16 + g) * HSTR + koff]);
                    lds64(a1, a3, &ws[(rm + mt * 16 + 8 + g) * HSTR + koff]);
#pragma unroll
                    for (int nt = 0; nt < 4; nt++)
                        mma_f16(acc[mt][nt][0], acc[mt][nt][1], acc[mt][nt][2], acc[mt][nt][3],
                                a0, a1, a2, a3, b0[nt], b1[nt]);
                }
            }
        }
    }
#undef FU_LDG
#undef FU_PROD

    // ---- rowsum reduce within 16-lane h-groups ----
#pragma unroll
    for (int i = 0; i < 4; i++) {
        float v = rsum[i];
#pragma unroll
        for (int off = 8; off; off >>= 1) v += __shfl_xor_sync(0xffffffffu, v, off);
        if (pp == 0) rowsum_s[prow[i]] = v;
    }
    __syncthreads();

    // ---- epilogue: normalize + bias + store ----
#pragma unroll
    for (int mt = 0; mt < 2; mt++) {
        int lrA = rm + mt * 16 + g;
        int lrB = lrA + 8;
        float invA = 1.0f / fmaxf(rowsum_s[lrA], 1e-12f);
        float invB = 1.0f / fmaxf(rowsum_s[lrB], 1e-12f);
#pragma unroll
        for (int nt = 0; nt < 4; nt++) {
            int bcol = n0 + nt * 8 + ctg * 2;
            float2 bv = *reinterpret_cast<const float2*>(&bias[bcol]);
            float* opA = out + (size_t)(i0 + lrA) * (NH * DO) + head * DO + bcol;
            float* opB = out + (size_t)(i0 + lrB) * (NH * DO) + head * DO + bcol;
            *reinterpret_cast<float2*>(opA) =
                make_float2(acc[mt][nt][0] * invA + bv.x, acc[mt][nt][1] * invA + bv.y);
            *reinterpret_cast<float2*>(opB) =
                make_float2(acc[mt][nt][2] * invB + bv.x, acc[mt][nt][3] * invB + bv.y);
        }
    }
}

// ======================================================================
extern "C" void kernel_launch(void* const* d_in, const int* in_sizes, int n_in,
                              void* d_out, int out_size) {
    const float* adj = (const float*)d_in[0];
    const float* x   = (const float*)d_in[1];
    const float* W   = (const float*)d_in[2];
    const float* al  = (const float*)d_in[3];
    const float* ar  = (const float*)d_in[4];
    const float* b   = (const float*)d_in[5];
    float* out = (float*)d_out;

    const int dyn = 4 * TILEH * sizeof(__half);   // 49152 B
    cudaFuncSetAttribute(k_fused, cudaFuncAttributeMaxDynamicSharedMemorySize, dyn);

    k_hgemm<<<Nn / 32, 256>>>(x, W, al, ar);
    k_fused<<<dim3(NH, Nn / BM), 512, dyn>>>(adj, b, out);
}